// round 1
// baseline (speedup 1.0000x reference)
#include <cuda_runtime.h>
#include <cuda_bf16.h>
#include <math.h>

// MSRSA fused attention, fp32 SIMT baseline.
// B=2, H=16, L=2048, D=128.
// One CTA = (b, h, 16-query tile). Scores for the full 16x2048 row block are
// materialized in shared memory, softmaxed in place, written to the attn
// output exactly once, then P·V is accumulated from smem with 1/rowsum folded
// into the output epilogue.
//
// Grid ordering: h innermost, so the 16 heads that share A/D rows run
// back-to-back and hit L2 for adjacency / distance matrices.

#define Bq 2
#define Hh 16
#define Ll 2048
#define Dd 128
#define QT 16
#define KT 64
#define NTHREADS 256
#define KROW 132              // padded K/V tile row stride in floats (33 x 16B -> conflict-free LDS.128)
#define INV_SCALE 0.08838834764831845f   // 1/sqrt(128)

__global__ void __launch_bounds__(NTHREADS)
msrsa_fused_kernel(const float* __restrict__ Q,
                   const float* __restrict__ K,
                   const float* __restrict__ V,
                   const float* __restrict__ A,
                   const float* __restrict__ Ds,
                   const float* __restrict__ wA,
                   const float* __restrict__ wD,
                   float* __restrict__ out,
                   float* __restrict__ attn) {
    extern __shared__ float sm[];
    float* Qs  = sm;                    // QT*Dd = 2048 floats
    float* KVs = sm + QT * Dd;          // KT*KROW = 8448 floats
    float* S   = KVs + KT * KROW;       // QT*Ll = 32768 floats
    __shared__ float s_inv[QT];

    const int t  = threadIdx.x;
    const int bx = blockIdx.x;
    const int h    = bx & (Hh - 1);
    const int rest = bx >> 4;
    const int qt   = rest & (Ll / QT - 1);
    const int b    = rest >> 7;
    const int q0   = qt * QT;

    const size_t bh = (size_t)(b * Hh + h);
    const float* Qb = Q + (bh * Ll + q0) * Dd;
    const float* Kb = K + bh * Ll * Dd;
    const float* Vb = V + bh * Ll * Dd;
    const float* Ab = A  + ((size_t)b * Ll + q0) * Ll;
    const float* Db = Ds + ((size_t)b * Ll + q0) * Ll;
    const float wa = wA[h];
    const float wd = wD[h];

    // ---- load Q tile (16x128, contiguous) ----
    {
        const float4* Qg4 = (const float4*)Qb;
        float4* Qs4 = (float4*)Qs;
        #pragma unroll
        for (int i = t; i < QT * Dd / 4; i += NTHREADS) Qs4[i] = Qg4[i];
    }

    const int qy = t >> 5;   // 0..7 : handles q rows {qy, qy+8}
    const int kx = t & 31;   // 0..31: handles k cols {kx, kx+32} within tile

    const float4* Qs4 = (const float4*)Qs;
    const float4* K4  = (const float4*)KVs;   // row stride 33 float4

    // ============ Phase 1: logits -> S ============
    for (int kt = 0; kt < Ll / KT; ++kt) {
        const int k0 = kt * KT;
        __syncthreads();
        // load K tile 64x128
        {
            const float4* Kg4 = (const float4*)(Kb + (size_t)k0 * Dd);
            #pragma unroll
            for (int i = t; i < KT * (Dd / 4); i += NTHREADS) {
                int r = i >> 5, c = i & 31;
                *(float4*)&KVs[r * KROW + c * 4] = Kg4[i];
            }
        }
        __syncthreads();

        float a00 = 0.f, a01 = 0.f, a10 = 0.f, a11 = 0.f;
        #pragma unroll
        for (int d4 = 0; d4 < Dd / 4; ++d4) {
            float4 qa = Qs4[qy * 32 + d4];
            float4 qb = Qs4[(qy + 8) * 32 + d4];
            float4 ka = K4[kx * 33 + d4];
            float4 kb = K4[(kx + 32) * 33 + d4];
            a00 += qa.x * ka.x + qa.y * ka.y + qa.z * ka.z + qa.w * ka.w;
            a01 += qa.x * kb.x + qa.y * kb.y + qa.z * kb.z + qa.w * kb.w;
            a10 += qb.x * ka.x + qb.y * ka.y + qb.z * ka.z + qb.w * ka.w;
            a11 += qb.x * kb.x + qb.y * kb.y + qb.z * kb.z + qb.w * kb.w;
        }

        // apply (1 + A*wa + D*wd)/scale, store logits
        {
            const int gk0 = k0 + kx, gk1 = k0 + kx + 32;
            const size_t r0 = (size_t)qy * Ll;
            const size_t r1 = (size_t)(qy + 8) * Ll;
            float m;
            m = 1.f + Ab[r0 + gk0] * wa + Db[r0 + gk0] * wd;
            S[qy * Ll + gk0] = a00 * m * INV_SCALE;
            m = 1.f + Ab[r0 + gk1] * wa + Db[r0 + gk1] * wd;
            S[qy * Ll + gk1] = a01 * m * INV_SCALE;
            m = 1.f + Ab[r1 + gk0] * wa + Db[r1 + gk0] * wd;
            S[(qy + 8) * Ll + gk0] = a10 * m * INV_SCALE;
            m = 1.f + Ab[r1 + gk1] * wa + Db[r1 + gk1] * wd;
            S[(qy + 8) * Ll + gk1] = a11 * m * INV_SCALE;
        }
    }
    __syncthreads();

    // ============ Phase 2: softmax in smem (warp w owns rows w, w+8) ============
    {
        const int w    = t >> 5;
        const int lane = t & 31;
        #pragma unroll
        for (int rsel = 0; rsel < 2; ++rsel) {
            const int rr = w + rsel * 8;
            float* row = S + rr * Ll;
            float m = -1e30f;
            for (int c = lane; c < Ll; c += 32) m = fmaxf(m, row[c]);
            #pragma unroll
            for (int o = 16; o > 0; o >>= 1) m = fmaxf(m, __shfl_xor_sync(0xffffffffu, m, o));
            float sum = 0.f;
            for (int c = lane; c < Ll; c += 32) {
                float e = __expf(row[c] - m);
                row[c] = e;
                sum += e;
            }
            #pragma unroll
            for (int o = 16; o > 0; o >>= 1) sum += __shfl_xor_sync(0xffffffffu, sum, o);
            if (lane == 0) s_inv[rr] = 1.f / sum;
        }
    }
    __syncthreads();

    // ============ Phase 3: write normalized attention weights ============
    {
        float* attn_base = attn + (bh * Ll + q0) * Ll;   // QT x L contiguous block
        const float4* S4 = (const float4*)S;
        float4* O4 = (float4*)attn_base;
        #pragma unroll 4
        for (int i = t; i < QT * Ll / 4; i += NTHREADS) {
            const int row = i >> 9;                      // 512 float4 per row
            const float inv = s_inv[row];
            float4 v = S4[i];
            v.x *= inv; v.y *= inv; v.z *= inv; v.w *= inv;
            O4[i] = v;
        }
    }

    // ============ Phase 4: out = (E / rowsum) @ V ============
    {
        const int dx = t & 31;    // d chunk (float4)
        float4 o0 = make_float4(0.f, 0.f, 0.f, 0.f);
        float4 o1 = make_float4(0.f, 0.f, 0.f, 0.f);
        for (int kt = 0; kt < Ll / KT; ++kt) {
            const int k0 = kt * KT;
            __syncthreads();
            {
                const float4* Vg4 = (const float4*)(Vb + (size_t)k0 * Dd);
                #pragma unroll
                for (int i = t; i < KT * (Dd / 4); i += NTHREADS) {
                    int r = i >> 5, c = i & 31;
                    *(float4*)&KVs[r * KROW + c * 4] = Vg4[i];
                }
            }
            __syncthreads();
            const float* Srow0 = S + qy * Ll + k0;
            const float* Srow1 = S + (qy + 8) * Ll + k0;
            #pragma unroll 8
            for (int k = 0; k < KT; ++k) {
                const float w0 = Srow0[k];
                const float w1 = Srow1[k];
                const float4 v = K4[k * 33 + dx];
                o0.x += w0 * v.x; o0.y += w0 * v.y; o0.z += w0 * v.z; o0.w += w0 * v.w;
                o1.x += w1 * v.x; o1.y += w1 * v.y; o1.z += w1 * v.z; o1.w += w1 * v.w;
            }
        }
        const float i0 = s_inv[qy];
        const float i1 = s_inv[qy + 8];
        o0.x *= i0; o0.y *= i0; o0.z *= i0; o0.w *= i0;
        o1.x *= i1; o1.y *= i1; o1.z *= i1; o1.w *= i1;
        float* outb = out + (bh * Ll + q0) * Dd;
        ((float4*)(outb + qy * Dd))[dx] = o0;
        ((float4*)(outb + (qy + 8) * Dd))[dx] = o1;
    }
}

extern "C" void kernel_launch(void* const* d_in, const int* in_sizes, int n_in,
                              void* d_out, int out_size) {
    (void)in_sizes; (void)n_in;
    const float* Q  = (const float*)d_in[0];
    const float* K  = (const float*)d_in[1];
    const float* V  = (const float*)d_in[2];
    const float* A  = (const float*)d_in[3];
    const float* Ds = (const float*)d_in[4];
    const float* wA = (const float*)d_in[5];
    const float* wD = (const float*)d_in[6];

    float* out  = (float*)d_out;                          // B*H*L*D = 8388608 floats
    float* attn = (float*)d_out + (size_t)Bq * Hh * Ll * Dd; // then B*H*L*L
    (void)out_size;

    const size_t smem = (size_t)(QT * Dd + KT * KROW + QT * Ll) * sizeof(float); // 173056 B
    cudaFuncSetAttribute(msrsa_fused_kernel,
                         cudaFuncAttributeMaxDynamicSharedMemorySize, (int)smem);

    dim3 grid(Bq * Hh * (Ll / QT));  // 4096 CTAs, h innermost
    msrsa_fused_kernel<<<grid, NTHREADS, smem>>>(Q, K, V, A, Ds, wA, wD, out, attn);
}